// round 14
// baseline (speedup 1.0000x reference)
#include <cuda_runtime.h>
#include <cuda_bf16.h>
#include <cstdint>

#define BB 1024
#define TT 512
#define L1P 511
#define P1 256
#define C1N 128
#define C2N 64
#define L2 128
#define HID 64
#define NG 256
#define EPSV 1e-5f

typedef unsigned long long ull;

// ---------------- device scratch ----------------
__device__ float g_y2[BB * P1 * C2N];        // conv2 output [b][p][c]
__device__ float g_shared[BB * HID];
__device__ float g_wihT[HID * NG];           // wih transposed [k][g]
__device__ float g_w2T[C1N * C2N];           // conv2 weights transposed [k][c]
__device__ float g_pstats[16];
__device__ float g_bn1A[C1N], g_bn1D[C1N];
__device__ float g_c2sum[C2N], g_c2sq[C2N];
__device__ float g_bn2A[C2N], g_bn2D[C2N];
__device__ float g_bsum[NG];

__device__ __forceinline__ float sigm(float v) { return __fdividef(1.f, 1.f + __expf(-v)); }
__device__ __forceinline__ float tanhx(float v) { return 1.f - __fdividef(2.f, __expf(2.f * v) + 1.f); }

// ---- f32x2 packed math helpers ----
__device__ __forceinline__ ull pk2(float a, float b) {
    ull r; asm("mov.b64 %0,{%1,%2};" : "=l"(r) : "f"(a), "f"(b)); return r;
}
__device__ __forceinline__ ull dup2(float a) {
    ull r; asm("mov.b64 %0,{%1,%1};" : "=l"(r) : "f"(a)); return r;
}
__device__ __forceinline__ void upk2(ull v, float& a, float& b) {
    asm("mov.b64 {%0,%1},%2;" : "=f"(a), "=f"(b) : "l"(v));
}
__device__ __forceinline__ ull ffma2(ull a, ull b, ull c) {
    ull d; asm("fma.rn.f32x2 %0,%1,%2,%3;" : "=l"(d) : "l"(a), "l"(b), "l"(c)); return d;
}

// ---------------- K0: zero accumulators ----------------
__global__ void k0_zero() {
    int t = threadIdx.x;
    if (t < 16) g_pstats[t] = 0.f;
    if (t < 64) { g_c2sum[t] = 0.f; g_c2sq[t] = 0.f; }
}

// ---------------- KT: transpose wih -> [k][g] ----------------
__global__ void kT_wih(const float* __restrict__ wih) {
    int idx = blockIdx.x * 256 + threadIdx.x;  // 0..16383
    int g = idx >> 6, k = idx & 63;
    g_wihT[k * NG + g] = wih[idx];
}

// ---------------- KW: transpose conv2 weights -> [k][c] ----------------
__global__ void kW_w2(const float* __restrict__ w2) {
    int idx = blockIdx.x * 256 + threadIdx.x;  // 0..8191
    int k = idx >> 6, c = idx & 63;
    g_w2T[idx] = w2[c * C1N + k];
}

// ---------------- K1: patch statistics (block-reduced atomics) ----------------
__global__ void __launch_bounds__(256) k1_pstats(const float* __restrict__ x) {
    __shared__ float red[8][14];
    const float2* x2 = (const float2*)x;
    float v[14];
#pragma unroll
    for (int i = 0; i < 14; i++) v[i] = 0.f;
    int total = BB * L1P;
    int stride = gridDim.x * blockDim.x;
#pragma unroll 4
    for (int idx = blockIdx.x * blockDim.x + threadIdx.x; idx < total; idx += stride) {
        int b = idx / L1P;
        int t = idx - b * L1P;
        float2 a = x2[b * TT + t];
        float2 c = x2[b * TT + t + 1];
        float p0 = a.x, p1 = a.y, p2 = c.x, p3 = c.y;
        v[0] += p0; v[1] += p1; v[2] += p2; v[3] += p3;
        v[4] += p0 * p0; v[5] += p0 * p1; v[6] += p0 * p2; v[7] += p0 * p3;
        v[8] += p1 * p1; v[9] += p1 * p2; v[10] += p1 * p3;
        v[11] += p2 * p2; v[12] += p2 * p3; v[13] += p3 * p3;
    }
    int wid = threadIdx.x >> 5, lane = threadIdx.x & 31;
#pragma unroll
    for (int i = 0; i < 14; i++) {
        float s = v[i];
#pragma unroll
        for (int o = 16; o > 0; o >>= 1) s += __shfl_xor_sync(0xffffffffu, s, o);
        if (lane == 0) red[wid][i] = s;
    }
    __syncthreads();
    if (threadIdx.x < 14) {
        int i = threadIdx.x;
        float s = red[0][i] + red[1][i] + red[2][i] + red[3][i]
                + red[4][i] + red[5][i] + red[6][i] + red[7][i];
        atomicAdd(&g_pstats[i], s);
    }
}

// ---------------- K2: BN1 affine from analytic stats ----------------
__global__ void k2_bn1(const float* __restrict__ w1, const float* __restrict__ b1,
                       const float* __restrict__ gg, const float* __restrict__ bbeta) {
    int c = threadIdx.x;  // 128
    float N = (float)(BB * L1P);
    float m0 = g_pstats[0] / N, m1 = g_pstats[1] / N, m2 = g_pstats[2] / N, m3 = g_pstats[3] / N;
    float M00 = g_pstats[4] / N, M01 = g_pstats[5] / N, M02 = g_pstats[6] / N, M03 = g_pstats[7] / N;
    float M11 = g_pstats[8] / N, M12 = g_pstats[9] / N, M13 = g_pstats[10] / N;
    float M22 = g_pstats[11] / N, M23 = g_pstats[12] / N, M33 = g_pstats[13] / N;
    float v0 = w1[c * 4 + 0], v1 = w1[c * 4 + 2], v2 = w1[c * 4 + 1], v3 = w1[c * 4 + 3];
    float bc = b1[c];
    float vm = v0 * m0 + v1 * m1 + v2 * m2 + v3 * m3;
    float mean = vm + bc;
    float q = v0 * v0 * M00 + v1 * v1 * M11 + v2 * v2 * M22 + v3 * v3 * M33
            + 2.f * (v0 * v1 * M01 + v0 * v2 * M02 + v0 * v3 * M03
                   + v1 * v2 * M12 + v1 * v3 * M13 + v2 * v3 * M23);
    float ey2 = q + 2.f * bc * vm + bc * bc;
    float var = ey2 - mean * mean;
    float A = gg[c] * rsqrtf(var + EPSV);
    g_bn1A[c] = A;
    g_bn1D[c] = bbeta[c] + A * (bc - mean);
}

// ---------------- K3: conv1+BN1+ReLU+pool1+conv2 fused (R10 proven version) ----------------
#define K3_HS   0
#define K3_WT   16896
#define K3_XS   25088
#define K3_SW   25608
#define K3_D1   26120
#define K3_B2   26248
#define K3_SUM  26312
#define K3_SQ   26376
#define K3_FLTS 26440
#define K3_SMEM (K3_FLTS * 4)

__global__ void __launch_bounds__(256, 1) k3_fused(const float* __restrict__ x,
                                                   const float* __restrict__ w1,
                                                   const float* __restrict__ b2) {
    extern __shared__ float sm3[];
    float* hs = sm3 + K3_HS;      // [k=128][p stride 132]
    float* wt2T = sm3 + K3_WT;    // [k=128][c=64]
    float* xs = sm3 + K3_XS;
    float* sw = sm3 + K3_SW;
    float* D1s = sm3 + K3_D1;
    float* b2s = sm3 + K3_B2;
    float* ssum = sm3 + K3_SUM;
    float* ssq = sm3 + K3_SQ;
    int tid = threadIdx.x;
    int b = blockIdx.y;
    int p0 = blockIdx.x * 128;

    if (tid < 128) {
        float A = g_bn1A[tid];
        sw[tid * 4 + 0] = A * w1[tid * 4 + 0];
        sw[tid * 4 + 1] = A * w1[tid * 4 + 2];
        sw[tid * 4 + 2] = A * w1[tid * 4 + 1];
        sw[tid * 4 + 3] = A * w1[tid * 4 + 3];
        D1s[tid] = g_bn1D[tid];
    }
    if (tid < 64) { b2s[tid] = b2[tid]; ssum[tid] = 0.f; ssq[tid] = 0.f; }
    {
        int tlo = 2 * p0 - 1;
        const float2* x2 = (const float2*)x;
        for (int j = tid; j < 258; j += 256) {
            int t = tlo + j;
            float2 vv = (t >= 0 && t < TT) ? x2[b * TT + t] : make_float2(0.f, 0.f);
            xs[2 * j] = vv.x;
            xs[2 * j + 1] = vv.y;
        }
    }
    {
        const float4* s4 = (const float4*)g_w2T;
        float4* d4 = (float4*)wt2T;
        for (int idx = tid; idx < C1N * C2N / 4; idx += 256) d4[idx] = s4[idx];
    }
    __syncthreads();

    const float4* xs4 = (const float4*)xs;
    for (int idx = tid; idx < C1N * 128; idx += 256) {
        int p = idx & 127, c = idx >> 7;
        float4 q1 = xs4[p];
        float4 q2 = xs4[p + 1];
        float s0 = sw[c * 4], s1 = sw[c * 4 + 1], s2 = sw[c * 4 + 2], s3 = sw[c * 4 + 3];
        float D = D1s[c];
        float z2 = fmaf(s0, q1.z, fmaf(s1, q1.w, fmaf(s2, q2.x, fmaf(s3, q2.y, D))));
        float z;
        if (p0 + p == 0) {
            z = z2;
        } else {
            float z1 = fmaf(s0, q1.x, fmaf(s1, q1.y, fmaf(s2, q1.z, fmaf(s3, q1.w, D))));
            z = fmaxf(z1, z2);
        }
        hs[c * 132 + p] = fmaxf(z, 0.f);
    }
    __syncthreads();

    int lane = tid & 31, w = tid >> 5;
    int pq2 = lane & 3, cq2 = lane >> 2;
    int pbase = w * 16 + pq2 * 4;
    int cbase = cq2 * 8;
    ull acc2[2][8];
#pragma unroll
    for (int i = 0; i < 2; i++)
#pragma unroll
        for (int j = 0; j < 8; j++) acc2[i][j] = 0ull;
#pragma unroll 4
    for (int k = 0; k < C1N; k++) {
        ulonglong2 hv = *(const ulonglong2*)&hs[k * 132 + pbase];
        float4 w0 = *(const float4*)&wt2T[k * C2N + cbase];
        float4 w1q = *(const float4*)&wt2T[k * C2N + cbase + 4];
        const float* w0f = (const float*)&w0;
        const float* w1f = (const float*)&w1q;
#pragma unroll
        for (int j = 0; j < 4; j++) {
            ull wd = dup2(w0f[j]);
            acc2[0][j] = ffma2(wd, hv.x, acc2[0][j]);
            acc2[1][j] = ffma2(wd, hv.y, acc2[1][j]);
        }
#pragma unroll
        for (int j = 0; j < 4; j++) {
            ull wd = dup2(w1f[j]);
            acc2[0][j + 4] = ffma2(wd, hv.x, acc2[0][j + 4]);
            acc2[1][j + 4] = ffma2(wd, hv.y, acc2[1][j + 4]);
        }
    }
    float csum[8], csq[8];
#pragma unroll
    for (int j = 0; j < 8; j++) { csum[j] = 0.f; csq[j] = 0.f; }
#pragma unroll
    for (int pr = 0; pr < 2; pr++) {
        float lo[8], hi[8];
#pragma unroll
        for (int j = 0; j < 8; j++) upk2(acc2[pr][j], lo[j], hi[j]);
#pragma unroll
        for (int half = 0; half < 2; half++) {
            int P = p0 + pbase + pr * 2 + half;
            float* src = half ? hi : lo;
            float4 o0, o1;
            float* q0 = (float*)&o0;
            float* q1 = (float*)&o1;
#pragma unroll
            for (int j = 0; j < 4; j++) {
                float v0 = src[j] + b2s[cbase + j];
                float v1 = src[j + 4] + b2s[cbase + 4 + j];
                q0[j] = v0; q1[j] = v1;
                csum[j] += v0; csq[j] += v0 * v0;
                csum[j + 4] += v1; csq[j + 4] += v1 * v1;
            }
            float* dst = &g_y2[((size_t)b * P1 + P) * C2N + cbase];
            *(float4*)dst = o0;
            *(float4*)(dst + 4) = o1;
        }
    }
#pragma unroll
    for (int o = 1; o <= 2; o <<= 1) {
#pragma unroll
        for (int j = 0; j < 8; j++) {
            csum[j] += __shfl_xor_sync(0xffffffffu, csum[j], o);
            csq[j] += __shfl_xor_sync(0xffffffffu, csq[j], o);
        }
    }
    if (pq2 == 0) {
#pragma unroll
        for (int j = 0; j < 8; j++) {
            atomicAdd(&ssum[cbase + j], csum[j]);
            atomicAdd(&ssq[cbase + j], csq[j]);
        }
    }
    __syncthreads();
    if (tid < 64) {
        atomicAdd(&g_c2sum[tid], ssum[tid]);
        atomicAdd(&g_c2sq[tid], ssq[tid]);
    }
}

// ---------------- K4: BN2 affine + LSTM bias sum ----------------
__global__ void k4_bn2(const float* __restrict__ g2, const float* __restrict__ be2,
                       const float* __restrict__ bih, const float* __restrict__ bhh) {
    int t = threadIdx.x;  // 256
    if (t < 64) {
        float N = (float)(BB * P1);
        float mean = g_c2sum[t] / N;
        float var = g_c2sq[t] / N - mean * mean;
        float A = g2[t] * rsqrtf(var + EPSV);
        g_bn2A[t] = A;
        g_bn2D[t] = be2[t] - A * mean;
    }
    g_bsum[t] = bih[t] + bhh[t];
}

// ---------------- K56: fused xgates + LSTM recurrence ----------------
// 128 blocks x 256 threads; 8 batch rows/block. Thread g owns gate g.
// gates[t] = bias + Wih·seq[t] + Whh·h[t-1]; seq[t+1] built in-kernel from y2.
#define K56_WSM 0
#define K56_G   16384
#define K56_H   18432
#define K56_S   18944
#define K56_A2  19712
#define K56_D2  19776
#define K56_FLTS 19840
#define K56_SMEM (K56_FLTS * 4)

__global__ void __launch_bounds__(256, 1) k56_fused(const float* __restrict__ whh) {
    extern __shared__ float sm6[];
    float* wsm = sm6 + K56_WSM;   // [k=64][g=256]
    float* G   = sm6 + K56_G;     // [r=8][g=256]
    float* hsm = sm6 + K56_H;     // [k=64][r=8]
    float* ssm = sm6 + K56_S;     // [k=64][stride 12]
    float* A2  = sm6 + K56_A2;
    float* D2  = sm6 + K56_D2;
    int tid = threadIdx.x;
    int g = tid;
    int b0 = blockIdx.x * 8;

    // load wihT tile
    {
        const float4* s4 = (const float4*)g_wihT;
        float4* d4 = (float4*)wsm;
        for (int i = tid; i < HID * NG / 4; i += 256) d4[i] = s4[i];
    }
    if (tid < 64) { A2[tid] = g_bn2A[tid]; D2[tid] = g_bn2D[tid]; }
    for (int i = tid; i < HID * 8; i += 256) hsm[i] = 0.f;

    // whh row in registers (dup2'd)
    ull wpack[64];
    {
        const float4* w4 = (const float4*)(whh + (size_t)g * 64);
#pragma unroll
        for (int q = 0; q < 16; q++) {
            float4 v = w4[q];
            wpack[4 * q]     = dup2(v.x);
            wpack[4 * q + 1] = dup2(v.y);
            wpack[4 * q + 2] = dup2(v.z);
            wpack[4 * q + 3] = dup2(v.w);
        }
    }
    ull bias2 = dup2(g_bsum[g]);

    int r_u = tid >> 5, lane = tid & 31;
    // stager mapping: warp = batch row tb; lanes 0-15 row 2l, 16-31 row 2l+1
    int tb = tid >> 5;
    int lh = lane & 15, rsel = lane >> 4;
    int c4 = lh * 4;
    __syncthreads();

    // prologue: seq for t=0
    {
        float4 y4 = *(const float4*)(g_y2 + ((size_t)(b0 + tb) * P1 + rsel) * C2N + c4);
        float z0 = fmaf(A2[c4 + 0], y4.x, D2[c4 + 0]);
        float z1 = fmaf(A2[c4 + 1], y4.y, D2[c4 + 1]);
        float z2 = fmaf(A2[c4 + 2], y4.z, D2[c4 + 2]);
        float z3 = fmaf(A2[c4 + 3], y4.w, D2[c4 + 3]);
        float m0 = fmaxf(fmaxf(z0, __shfl_xor_sync(0xffffffffu, z0, 16)), 0.f);
        float m1 = fmaxf(fmaxf(z1, __shfl_xor_sync(0xffffffffu, z1, 16)), 0.f);
        float m2 = fmaxf(fmaxf(z2, __shfl_xor_sync(0xffffffffu, z2, 16)), 0.f);
        float m3 = fmaxf(fmaxf(z3, __shfl_xor_sync(0xffffffffu, z3, 16)), 0.f);
        if (rsel == 0) {
            ssm[(c4 + 0) * 12 + tb] = m0;
            ssm[(c4 + 1) * 12 + tb] = m1;
            ssm[(c4 + 2) * 12 + tb] = m2;
            ssm[(c4 + 3) * 12 + tb] = m3;
        }
    }
    float c0 = 0.f, c1 = 0.f, hs0 = 0.f, hs1 = 0.f;
    __syncthreads();

    for (int t = 0; t < L2; t++) {
        // prefetch y2 for seq[t+1] (latency hidden under GEMM)
        float4 y4 = make_float4(0.f, 0.f, 0.f, 0.f);
        if (t + 1 < L2)
            y4 = *(const float4*)(g_y2 + ((size_t)(b0 + tb) * P1 + 2 * (t + 1) + rsel) * C2N + c4);

        // combined GEMM: bias + Wih·seq + Whh·h, 8 rows packed as 4 f32x2
        ull a0 = bias2, a1 = bias2, a2v = bias2, a3 = bias2;
#pragma unroll 4
        for (int k = 0; k < HID; k++) {
            ull wd = dup2(wsm[k * NG + g]);
            ulonglong2 hA = *(const ulonglong2*)&hsm[k * 8];
            ulonglong2 hB = *(const ulonglong2*)&hsm[k * 8 + 4];
            ulonglong2 sA = *(const ulonglong2*)&ssm[k * 12];
            ulonglong2 sB = *(const ulonglong2*)&ssm[k * 12 + 4];
            a0 = ffma2(wpack[k], hA.x, a0);  a0 = ffma2(wd, sA.x, a0);
            a1 = ffma2(wpack[k], hA.y, a1);  a1 = ffma2(wd, sA.y, a1);
            a2v = ffma2(wpack[k], hB.x, a2v); a2v = ffma2(wd, sB.x, a2v);
            a3 = ffma2(wpack[k], hB.y, a3);  a3 = ffma2(wd, sB.y, a3);
        }
        {
            float u, v_;
            upk2(a0, u, v_);  G[0 * 256 + g] = u; G[1 * 256 + g] = v_;
            upk2(a1, u, v_);  G[2 * 256 + g] = u; G[3 * 256 + g] = v_;
            upk2(a2v, u, v_); G[4 * 256 + g] = u; G[5 * 256 + g] = v_;
            upk2(a3, u, v_);  G[6 * 256 + g] = u; G[7 * 256 + g] = v_;
        }
        __syncthreads();
        // cell update: warp r_u handles row r_u, lane = cell (and cell+32)
        {
            int r = r_u;
            float gi0 = G[r * 256 + lane],       gi1 = G[r * 256 + lane + 32];
            float gf0 = G[r * 256 + 64 + lane],  gf1 = G[r * 256 + 96 + lane];
            float gg0 = G[r * 256 + 128 + lane], gg1 = G[r * 256 + 160 + lane];
            float go0 = G[r * 256 + 192 + lane], go1 = G[r * 256 + 224 + lane];
            c0 = sigm(gf0) * c0 + sigm(gi0) * tanhx(gg0);
            c1 = sigm(gf1) * c1 + sigm(gi1) * tanhx(gg1);
            float h0 = sigm(go0) * tanhx(c0);
            float h1 = sigm(go1) * tanhx(c1);
            hs0 += h0; hs1 += h1;
            hsm[lane * 8 + r] = h0;
            hsm[(lane + 32) * 8 + r] = h1;
        }
        // seq[t+1]: BN + pool-max + relu, write ssm
        if (t + 1 < L2) {
            float z0 = fmaf(A2[c4 + 0], y4.x, D2[c4 + 0]);
            float z1 = fmaf(A2[c4 + 1], y4.y, D2[c4 + 1]);
            float z2 = fmaf(A2[c4 + 2], y4.z, D2[c4 + 2]);
            float z3 = fmaf(A2[c4 + 3], y4.w, D2[c4 + 3]);
            float m0 = fmaxf(fmaxf(z0, __shfl_xor_sync(0xffffffffu, z0, 16)), 0.f);
            float m1 = fmaxf(fmaxf(z1, __shfl_xor_sync(0xffffffffu, z1, 16)), 0.f);
            float m2 = fmaxf(fmaxf(z2, __shfl_xor_sync(0xffffffffu, z2, 16)), 0.f);
            float m3 = fmaxf(fmaxf(z3, __shfl_xor_sync(0xffffffffu, z3, 16)), 0.f);
            if (rsel == 0) {
                ssm[(c4 + 0) * 12 + tb] = m0;
                ssm[(c4 + 1) * 12 + tb] = m1;
                ssm[(c4 + 2) * 12 + tb] = m2;
                ssm[(c4 + 3) * 12 + tb] = m3;
            }
        }
        __syncthreads();
    }
    g_shared[(b0 + r_u) * 64 + lane] = hs0 * (1.f / 128.f);
    g_shared[(b0 + r_u) * 64 + lane + 32] = hs1 * (1.f / 128.f);
}

// ---------------- K8: task-routed heads ----------------
__global__ void __launch_bounds__(128) k8_heads(const int* __restrict__ task_ids,
                                                const float* __restrict__ W1, const float* __restrict__ b1,
                                                const float* __restrict__ W2, const float* __restrict__ b2,
                                                const float* __restrict__ Wo, const float* __restrict__ bo,
                                                float* __restrict__ out) {
    __shared__ float sh[64], h1s[128], h2s[64];
    int b = blockIdx.x, tid = threadIdx.x;
    if (tid < 64) sh[tid] = g_shared[b * 64 + tid];
    __syncthreads();
    int task = task_ids[b];
    {
        const float4* w = (const float4*)(W1 + ((size_t)task * 128 + tid) * 64);
        float acc = b1[task * 128 + tid];
#pragma unroll
        for (int q = 0; q < 16; q++) {
            float4 v = w[q];
            acc += v.x * sh[4 * q] + v.y * sh[4 * q + 1] + v.z * sh[4 * q + 2] + v.w * sh[4 * q + 3];
        }
        h1s[tid] = fmaxf(acc, 0.f);
    }
    __syncthreads();
    if (tid < 64) {
        const float4* w = (const float4*)(W2 + ((size_t)task * 64 + tid) * 128);
        float acc = b2[task * 64 + tid];
#pragma unroll
        for (int q = 0; q < 32; q++) {
            float4 v = w[q];
            acc += v.x * h1s[4 * q] + v.y * h1s[4 * q + 1] + v.z * h1s[4 * q + 2] + v.w * h1s[4 * q + 3];
        }
        h2s[tid] = fmaxf(acc, 0.f);
    }
    __syncthreads();
    if (tid < 32) {
        float p = Wo[task * 64 + tid] * h2s[tid] + Wo[task * 64 + tid + 32] * h2s[tid + 32];
#pragma unroll
        for (int o = 16; o > 0; o >>= 1) p += __shfl_xor_sync(0xffffffffu, p, o);
        if (tid == 0) out[b] = p + bo[task];
    }
}

// ---------------- launch ----------------
extern "C" void kernel_launch(void* const* d_in, const int* in_sizes, int n_in,
                              void* d_out, int out_size) {
    const float* x       = (const float*)d_in[0];
    const int*   task_ids= (const int*)d_in[1];
    const float* conv1_w = (const float*)d_in[2];
    const float* conv1_b = (const float*)d_in[3];
    const float* bn1_g   = (const float*)d_in[4];
    const float* bn1_b   = (const float*)d_in[5];
    const float* conv2_w = (const float*)d_in[6];
    const float* conv2_b = (const float*)d_in[7];
    const float* bn2_g   = (const float*)d_in[8];
    const float* bn2_b   = (const float*)d_in[9];
    const float* wih     = (const float*)d_in[10];
    const float* whh     = (const float*)d_in[11];
    const float* bih     = (const float*)d_in[12];
    const float* bhh     = (const float*)d_in[13];
    const float* W1      = (const float*)d_in[14];
    const float* b1      = (const float*)d_in[15];
    const float* W2      = (const float*)d_in[16];
    const float* b2      = (const float*)d_in[17];
    const float* Wo      = (const float*)d_in[18];
    const float* bo      = (const float*)d_in[19];
    float* out = (float*)d_out;

    cudaFuncSetAttribute(k3_fused, cudaFuncAttributeMaxDynamicSharedMemorySize, K3_SMEM);
    cudaFuncSetAttribute(k56_fused, cudaFuncAttributeMaxDynamicSharedMemorySize, K56_SMEM);

    k0_zero<<<1, 64>>>();
    kT_wih<<<64, 256>>>(wih);
    kW_w2<<<32, 256>>>(conv2_w);
    k1_pstats<<<1024, 256>>>(x);
    k2_bn1<<<1, 128>>>(conv1_w, conv1_b, bn1_g, bn1_b);
    k3_fused<<<dim3(2, BB), 256, K3_SMEM>>>(x, conv1_w, conv2_b);
    k4_bn2<<<1, 256>>>(bn2_g, bn2_b, bih, bhh);
    k56_fused<<<128, 256, K56_SMEM>>>(whh);
    k8_heads<<<BB, 128>>>(task_ids, W1, b1, W2, b2, Wo, bo, out);
}

// round 15
// speedup vs baseline: 1.4771x; 1.4771x over previous
#include <cuda_runtime.h>
#include <cuda_bf16.h>
#include <cstdint>

#define BB 1024
#define TT 512
#define L1P 511
#define P1 256
#define C1N 128
#define C2N 64
#define L2 128
#define HID 64
#define NG 256
#define EPSV 1e-5f

typedef unsigned long long ull;

// ---------------- device scratch ----------------
__device__ float g_y2[BB * P1 * C2N];        // conv2 output [b][p][c]
__device__ float g_xg[(size_t)L2 * BB * NG]; // xgates [t][b][g]
__device__ float g_shared[BB * HID];
__device__ float g_wihT[HID * NG];           // wih transposed [k][g]
__device__ float g_w2T[C1N * C2N];           // conv2 weights transposed [k][c]
__device__ float g_pstats[16];
__device__ float g_c2sum[C2N], g_c2sq[C2N];

__device__ __forceinline__ float sigm(float v) { return __fdividef(1.f, 1.f + __expf(-v)); }
__device__ __forceinline__ float tanhx(float v) { return 1.f - __fdividef(2.f, __expf(2.f * v) + 1.f); }

// ---- f32x2 packed math helpers ----
__device__ __forceinline__ ull pk2(float a, float b) {
    ull r; asm("mov.b64 %0,{%1,%2};" : "=l"(r) : "f"(a), "f"(b)); return r;
}
__device__ __forceinline__ ull dup2(float a) {
    ull r; asm("mov.b64 %0,{%1,%1};" : "=l"(r) : "f"(a)); return r;
}
__device__ __forceinline__ void upk2(ull v, float& a, float& b) {
    asm("mov.b64 {%0,%1},%2;" : "=f"(a), "=f"(b) : "l"(v));
}
__device__ __forceinline__ ull ffma2(ull a, ull b, ull c) {
    ull d; asm("fma.rn.f32x2 %0,%1,%2,%3;" : "=l"(d) : "l"(a), "l"(b), "l"(c)); return d;
}

// ---------------- KPrep: transposes + zeroing (merged k0/kT/kW) ----------------
__global__ void kprep(const float* __restrict__ wih, const float* __restrict__ w2) {
    int bid = blockIdx.x;
    int tid = threadIdx.x;
    if (bid < 64) {
        int idx = bid * 256 + tid;          // 0..16383
        int g = idx >> 6, k = idx & 63;
        g_wihT[k * NG + g] = wih[idx];
    } else if (bid < 96) {
        int idx = (bid - 64) * 256 + tid;   // 0..8191
        int k = idx >> 6, c = idx & 63;
        g_w2T[idx] = w2[c * C1N + k];
    } else {
        if (tid < 16) g_pstats[tid] = 0.f;
        if (tid >= 32 && tid < 96) { g_c2sum[tid - 32] = 0.f; g_c2sq[tid - 32] = 0.f; }
    }
}

// ---------------- K1: patch statistics (block-reduced atomics) ----------------
__global__ void __launch_bounds__(256) k1_pstats(const float* __restrict__ x) {
    __shared__ float red[8][14];
    const float2* x2 = (const float2*)x;
    float v[14];
#pragma unroll
    for (int i = 0; i < 14; i++) v[i] = 0.f;
    int total = BB * L1P;
    int stride = gridDim.x * blockDim.x;
#pragma unroll 4
    for (int idx = blockIdx.x * blockDim.x + threadIdx.x; idx < total; idx += stride) {
        int b = idx / L1P;
        int t = idx - b * L1P;
        float2 a = x2[b * TT + t];
        float2 c = x2[b * TT + t + 1];
        float p0 = a.x, p1 = a.y, p2 = c.x, p3 = c.y;
        v[0] += p0; v[1] += p1; v[2] += p2; v[3] += p3;
        v[4] += p0 * p0; v[5] += p0 * p1; v[6] += p0 * p2; v[7] += p0 * p3;
        v[8] += p1 * p1; v[9] += p1 * p2; v[10] += p1 * p3;
        v[11] += p2 * p2; v[12] += p2 * p3; v[13] += p3 * p3;
    }
    int wid = threadIdx.x >> 5, lane = threadIdx.x & 31;
#pragma unroll
    for (int i = 0; i < 14; i++) {
        float s = v[i];
#pragma unroll
        for (int o = 16; o > 0; o >>= 1) s += __shfl_xor_sync(0xffffffffu, s, o);
        if (lane == 0) red[wid][i] = s;
    }
    __syncthreads();
    if (threadIdx.x < 14) {
        int i = threadIdx.x;
        float s = red[0][i] + red[1][i] + red[2][i] + red[3][i]
                + red[4][i] + red[5][i] + red[6][i] + red[7][i];
        atomicAdd(&g_pstats[i], s);
    }
}

// ---------------- K3: conv1+BN1+ReLU+pool1+conv2 fused (+BN2 stat accum) ----------------
// BN1 affine computed in-prolog from analytic stats (k2 folded in).
#define K3_HS   0
#define K3_WT   16896
#define K3_XS   25088
#define K3_SW   25608
#define K3_D1   26120
#define K3_B2   26248
#define K3_SUM  26312
#define K3_SQ   26376
#define K3_FLTS 26440
#define K3_SMEM (K3_FLTS * 4)

__global__ void __launch_bounds__(256, 1) k3_fused(const float* __restrict__ x,
                                                   const float* __restrict__ w1,
                                                   const float* __restrict__ b1,
                                                   const float* __restrict__ g1,
                                                   const float* __restrict__ be1,
                                                   const float* __restrict__ b2) {
    extern __shared__ float sm3[];
    float* hs = sm3 + K3_HS;      // [k=128][p stride 132]
    float* wt2T = sm3 + K3_WT;    // [k=128][c=64]
    float* xs = sm3 + K3_XS;
    float* sw = sm3 + K3_SW;
    float* D1s = sm3 + K3_D1;
    float* b2s = sm3 + K3_B2;
    float* ssum = sm3 + K3_SUM;
    float* ssq = sm3 + K3_SQ;
    int tid = threadIdx.x;
    int b = blockIdx.y;
    int p0 = blockIdx.x * 128;

    if (tid < 128) {
        // ---- BN1 affine from analytic patch stats (was k2) ----
        int c = tid;
        float N = (float)(BB * L1P);
        float m0 = g_pstats[0] / N, m1 = g_pstats[1] / N, m2 = g_pstats[2] / N, m3 = g_pstats[3] / N;
        float M00 = g_pstats[4] / N, M01 = g_pstats[5] / N, M02 = g_pstats[6] / N, M03 = g_pstats[7] / N;
        float M11 = g_pstats[8] / N, M12 = g_pstats[9] / N, M13 = g_pstats[10] / N;
        float M22 = g_pstats[11] / N, M23 = g_pstats[12] / N, M33 = g_pstats[13] / N;
        float v0 = w1[c * 4 + 0], v1 = w1[c * 4 + 2], v2 = w1[c * 4 + 1], v3 = w1[c * 4 + 3];
        float bc = b1[c];
        float vm = v0 * m0 + v1 * m1 + v2 * m2 + v3 * m3;
        float mean = vm + bc;
        float q = v0 * v0 * M00 + v1 * v1 * M11 + v2 * v2 * M22 + v3 * v3 * M33
                + 2.f * (v0 * v1 * M01 + v0 * v2 * M02 + v0 * v3 * M03
                       + v1 * v2 * M12 + v1 * v3 * M13 + v2 * v3 * M23);
        float ey2 = q + 2.f * bc * vm + bc * bc;
        float var = ey2 - mean * mean;
        float A = g1[c] * rsqrtf(var + EPSV);
        float D = be1[c] + A * (bc - mean);
        sw[c * 4 + 0] = A * v0;
        sw[c * 4 + 1] = A * v1;
        sw[c * 4 + 2] = A * v2;
        sw[c * 4 + 3] = A * v3;
        D1s[c] = D;
    }
    if (tid < 64) { b2s[tid] = b2[tid]; ssum[tid] = 0.f; ssq[tid] = 0.f; }
    {
        int tlo = 2 * p0 - 1;
        const float2* x2 = (const float2*)x;
        for (int j = tid; j < 258; j += 256) {
            int t = tlo + j;
            float2 vv = (t >= 0 && t < TT) ? x2[b * TT + t] : make_float2(0.f, 0.f);
            xs[2 * j] = vv.x;
            xs[2 * j + 1] = vv.y;
        }
    }
    {
        const float4* s4 = (const float4*)g_w2T;
        float4* d4 = (float4*)wt2T;
        for (int idx = tid; idx < C1N * C2N / 4; idx += 256) d4[idx] = s4[idx];
    }
    __syncthreads();

    const float4* xs4 = (const float4*)xs;
    for (int idx = tid; idx < C1N * 128; idx += 256) {
        int p = idx & 127, c = idx >> 7;
        float4 q1 = xs4[p];
        float4 q2 = xs4[p + 1];
        float s0 = sw[c * 4], s1 = sw[c * 4 + 1], s2 = sw[c * 4 + 2], s3 = sw[c * 4 + 3];
        float D = D1s[c];
        float z2 = fmaf(s0, q1.z, fmaf(s1, q1.w, fmaf(s2, q2.x, fmaf(s3, q2.y, D))));
        float z;
        if (p0 + p == 0) {
            z = z2;
        } else {
            float z1 = fmaf(s0, q1.x, fmaf(s1, q1.y, fmaf(s2, q1.z, fmaf(s3, q1.w, D))));
            z = fmaxf(z1, z2);
        }
        hs[c * 132 + p] = fmaxf(z, 0.f);
    }
    __syncthreads();

    int lane = tid & 31, w = tid >> 5;
    int pq2 = lane & 3, cq2 = lane >> 2;
    int pbase = w * 16 + pq2 * 4;
    int cbase = cq2 * 8;
    ull acc2[2][8];
#pragma unroll
    for (int i = 0; i < 2; i++)
#pragma unroll
        for (int j = 0; j < 8; j++) acc2[i][j] = 0ull;
#pragma unroll 4
    for (int k = 0; k < C1N; k++) {
        ulonglong2 hv = *(const ulonglong2*)&hs[k * 132 + pbase];
        float4 w0 = *(const float4*)&wt2T[k * C2N + cbase];
        float4 w1q = *(const float4*)&wt2T[k * C2N + cbase + 4];
        const float* w0f = (const float*)&w0;
        const float* w1f = (const float*)&w1q;
#pragma unroll
        for (int j = 0; j < 4; j++) {
            ull wd = dup2(w0f[j]);
            acc2[0][j] = ffma2(wd, hv.x, acc2[0][j]);
            acc2[1][j] = ffma2(wd, hv.y, acc2[1][j]);
        }
#pragma unroll
        for (int j = 0; j < 4; j++) {
            ull wd = dup2(w1f[j]);
            acc2[0][j + 4] = ffma2(wd, hv.x, acc2[0][j + 4]);
            acc2[1][j + 4] = ffma2(wd, hv.y, acc2[1][j + 4]);
        }
    }
    float csum[8], csq[8];
#pragma unroll
    for (int j = 0; j < 8; j++) { csum[j] = 0.f; csq[j] = 0.f; }
#pragma unroll
    for (int pr = 0; pr < 2; pr++) {
        float lo[8], hi[8];
#pragma unroll
        for (int j = 0; j < 8; j++) upk2(acc2[pr][j], lo[j], hi[j]);
#pragma unroll
        for (int half = 0; half < 2; half++) {
            int P = p0 + pbase + pr * 2 + half;
            float* src = half ? hi : lo;
            float4 o0, o1;
            float* q0 = (float*)&o0;
            float* q1 = (float*)&o1;
#pragma unroll
            for (int j = 0; j < 4; j++) {
                float v0 = src[j] + b2s[cbase + j];
                float v1 = src[j + 4] + b2s[cbase + 4 + j];
                q0[j] = v0; q1[j] = v1;
                csum[j] += v0; csq[j] += v0 * v0;
                csum[j + 4] += v1; csq[j + 4] += v1 * v1;
            }
            float* dst = &g_y2[((size_t)b * P1 + P) * C2N + cbase];
            *(float4*)dst = o0;
            *(float4*)(dst + 4) = o1;
        }
    }
#pragma unroll
    for (int o = 1; o <= 2; o <<= 1) {
#pragma unroll
        for (int j = 0; j < 8; j++) {
            csum[j] += __shfl_xor_sync(0xffffffffu, csum[j], o);
            csq[j] += __shfl_xor_sync(0xffffffffu, csq[j], o);
        }
    }
    if (pq2 == 0) {
#pragma unroll
        for (int j = 0; j < 8; j++) {
            atomicAdd(&ssum[cbase + j], csum[j]);
            atomicAdd(&ssq[cbase + j], csq[j]);
        }
    }
    __syncthreads();
    if (tid < 64) {
        atomicAdd(&g_c2sum[tid], ssum[tid]);
        atomicAdd(&g_c2sq[tid], ssq[tid]);
    }
}

// ---------------- K5: BN2+ReLU+pool2 + xgates GEMM (f32x2; BN2 affine in-prolog) ----------------
#define K5_W    0
#define K5_SS   16384
#define K5_C2   20736
#define K5_D2   20800
#define K5_BS   20864
#define K5_FLTS 21120
#define K5_SMEM (K5_FLTS * 4)

__global__ void __launch_bounds__(256, 1) k5_xgates(const float* __restrict__ g2,
                                                    const float* __restrict__ be2,
                                                    const float* __restrict__ bih,
                                                    const float* __restrict__ bhh) {
    extern __shared__ float sm5[];
    float* wsm = sm5 + K5_W;
    float* ss = sm5 + K5_SS;
    float* C2s = sm5 + K5_C2;
    float* D2s = sm5 + K5_D2;
    float* bs = sm5 + K5_BS;
    int tid = threadIdx.x;
    int r0 = blockIdx.x * 64;
    int b = r0 >> 7;
    int l0 = r0 & 127;
    if (tid < 64) {
        // ---- BN2 affine from accumulated stats (was k4) ----
        float N = (float)(BB * P1);
        float mean = g_c2sum[tid] / N;
        float var = g_c2sq[tid] / N - mean * mean;
        float A = g2[tid] * rsqrtf(var + EPSV);
        C2s[tid] = A;
        D2s[tid] = be2[tid] - A * mean;
    }
    bs[tid] = bih[tid] + bhh[tid];
    {
        const float4* wi4 = (const float4*)g_wihT;
        float4* ws4 = (float4*)wsm;
        for (int idx = tid; idx < NG * HID / 4; idx += 256) ws4[idx] = wi4[idx];
    }
    __syncthreads();
    for (int idx = tid; idx < 64 * 16; idx += 256) {
        int rl = idx >> 4, cq = idx & 15;
        int l = l0 + rl;
        const float4* ya4 = (const float4*)&g_y2[((size_t)b * P1 + 2 * l) * C2N];
        float4 ya = ya4[cq];
        float4 yb = ya4[16 + cq];
        float av[4] = {ya.x, ya.y, ya.z, ya.w};
        float bv[4] = {yb.x, yb.y, yb.z, yb.w};
#pragma unroll
        for (int j = 0; j < 4; j++) {
            int c = cq * 4 + j;
            float za = fmaf(C2s[c], av[j], D2s[c]);
            float zb = fmaf(C2s[c], bv[j], D2s[c]);
            ss[c * 68 + rl] = fmaxf(fmaxf(za, zb), 0.f);
        }
    }
    __syncthreads();
    int ro = tid >> 5, go = tid & 31;
    ull acc2[4][8];
#pragma unroll
    for (int i = 0; i < 4; i++)
#pragma unroll
        for (int j = 0; j < 8; j++) acc2[i][j] = 0ull;
#pragma unroll 4
    for (int k = 0; k < HID; k++) {
        ulonglong2 hA = *(const ulonglong2*)&ss[k * 68 + ro * 8];
        ulonglong2 hB = *(const ulonglong2*)&ss[k * 68 + ro * 8 + 4];
        float4 w0 = *(const float4*)&wsm[k * NG + go * 4];
        float4 w1 = *(const float4*)&wsm[k * NG + 128 + go * 4];
        const float* w0f = (const float*)&w0;
        const float* w1f = (const float*)&w1;
#pragma unroll
        for (int j = 0; j < 4; j++) {
            ull wd = dup2(w0f[j]);
            acc2[0][j] = ffma2(wd, hA.x, acc2[0][j]);
            acc2[1][j] = ffma2(wd, hA.y, acc2[1][j]);
            acc2[2][j] = ffma2(wd, hB.x, acc2[2][j]);
            acc2[3][j] = ffma2(wd, hB.y, acc2[3][j]);
        }
#pragma unroll
        for (int j = 0; j < 4; j++) {
            ull wd = dup2(w1f[j]);
            acc2[0][j + 4] = ffma2(wd, hA.x, acc2[0][j + 4]);
            acc2[1][j + 4] = ffma2(wd, hA.y, acc2[1][j + 4]);
            acc2[2][j + 4] = ffma2(wd, hB.x, acc2[2][j + 4]);
            acc2[3][j + 4] = ffma2(wd, hB.y, acc2[3][j + 4]);
        }
    }
#pragma unroll
    for (int pr = 0; pr < 4; pr++) {
        float lo[8], hi[8];
#pragma unroll
        for (int j = 0; j < 8; j++) upk2(acc2[pr][j], lo[j], hi[j]);
        int l = l0 + ro * 8 + pr * 2;
        float* d0 = &g_xg[((size_t)l * BB + b) * NG];
        float* d1 = &g_xg[((size_t)(l + 1) * BB + b) * NG];
        float4 a0, a1, b0q, b1q;
        float* pa0 = (float*)&a0; float* pa1 = (float*)&a1;
        float* pb0 = (float*)&b0q; float* pb1 = (float*)&b1q;
#pragma unroll
        for (int j = 0; j < 4; j++) {
            pa0[j] = lo[j] + bs[go * 4 + j];
            pa1[j] = lo[j + 4] + bs[128 + go * 4 + j];
            pb0[j] = hi[j] + bs[go * 4 + j];
            pb1[j] = hi[j + 4] + bs[128 + go * 4 + j];
        }
        *(float4*)(d0 + go * 4) = a0;
        *(float4*)(d0 + 128 + go * 4) = a1;
        *(float4*)(d1 + go * 4) = b0q;
        *(float4*)(d1 + 128 + go * 4) = b1q;
    }
}

// ---------------- K6: LSTM recurrence (f32x2, 8 rows/block) ----------------
__global__ void __launch_bounds__(256, 1) k6_lstm(const float* __restrict__ whh) {
    __shared__ float G[8 * 256];
    __shared__ __align__(16) float hsm[HID * 8];  // [k][r]
    int tid = threadIdx.x;
    int b0 = blockIdx.x * 8;
    int g = tid;
    ull wpack[64];
    {
        const float4* w4 = (const float4*)(whh + (size_t)g * 64);
#pragma unroll
        for (int q = 0; q < 16; q++) {
            float4 v = w4[q];
            wpack[4 * q] = dup2(v.x);
            wpack[4 * q + 1] = dup2(v.y);
            wpack[4 * q + 2] = dup2(v.z);
            wpack[4 * q + 3] = dup2(v.w);
        }
    }
    for (int idx = tid; idx < HID * 8; idx += 256) hsm[idx] = 0.f;
    int r_u = tid >> 5, lane = tid & 31;
    float c0 = 0.f, c1 = 0.f, hsum0 = 0.f, hsum1 = 0.f;
    float xv[8];
#pragma unroll
    for (int r = 0; r < 8; r++) xv[r] = g_xg[(size_t)(b0 + r) * NG + g];
    __syncthreads();
    for (int t = 0; t < L2; t++) {
        ull acc2[4];
#pragma unroll
        for (int p = 0; p < 4; p++) acc2[p] = pk2(xv[2 * p], xv[2 * p + 1]);
#pragma unroll
        for (int k = 0; k < HID; k++) {
            ulonglong2 hA = *(const ulonglong2*)&hsm[k * 8];
            ulonglong2 hB = *(const ulonglong2*)&hsm[k * 8 + 4];
            acc2[0] = ffma2(wpack[k], hA.x, acc2[0]);
            acc2[1] = ffma2(wpack[k], hA.y, acc2[1]);
            acc2[2] = ffma2(wpack[k], hB.x, acc2[2]);
            acc2[3] = ffma2(wpack[k], hB.y, acc2[3]);
        }
        if (t + 1 < L2) {
#pragma unroll
            for (int r = 0; r < 8; r++)
                xv[r] = g_xg[((size_t)(t + 1) * BB + b0 + r) * NG + g];
        }
#pragma unroll
        for (int p = 0; p < 4; p++) {
            float a, bq;
            upk2(acc2[p], a, bq);
            G[(2 * p) * 256 + g] = a;
            G[(2 * p + 1) * 256 + g] = bq;
        }
        __syncthreads();
        {
            int r = r_u;
            float gi0 = G[r * 256 + lane],       gi1 = G[r * 256 + lane + 32];
            float gf0 = G[r * 256 + 64 + lane],  gf1 = G[r * 256 + 96 + lane];
            float gg0 = G[r * 256 + 128 + lane], gg1 = G[r * 256 + 160 + lane];
            float go0 = G[r * 256 + 192 + lane], go1 = G[r * 256 + 224 + lane];
            c0 = sigm(gf0) * c0 + sigm(gi0) * tanhx(gg0);
            c1 = sigm(gf1) * c1 + sigm(gi1) * tanhx(gg1);
            float h0 = sigm(go0) * tanhx(c0);
            float h1 = sigm(go1) * tanhx(c1);
            hsum0 += h0; hsum1 += h1;
            hsm[lane * 8 + r] = h0;
            hsm[(lane + 32) * 8 + r] = h1;
        }
        __syncthreads();
    }
    g_shared[(b0 + r_u) * 64 + lane] = hsum0 * (1.f / 128.f);
    g_shared[(b0 + r_u) * 64 + lane + 32] = hsum1 * (1.f / 128.f);
}

// ---------------- K8: task-routed heads ----------------
__global__ void __launch_bounds__(128) k8_heads(const int* __restrict__ task_ids,
                                                const float* __restrict__ W1, const float* __restrict__ b1,
                                                const float* __restrict__ W2, const float* __restrict__ b2,
                                                const float* __restrict__ Wo, const float* __restrict__ bo,
                                                float* __restrict__ out) {
    __shared__ float sh[64], h1s[128], h2s[64];
    int b = blockIdx.x, tid = threadIdx.x;
    if (tid < 64) sh[tid] = g_shared[b * 64 + tid];
    __syncthreads();
    int task = task_ids[b];
    {
        const float4* w = (const float4*)(W1 + ((size_t)task * 128 + tid) * 64);
        float acc = b1[task * 128 + tid];
#pragma unroll
        for (int q = 0; q < 16; q++) {
            float4 v = w[q];
            acc += v.x * sh[4 * q] + v.y * sh[4 * q + 1] + v.z * sh[4 * q + 2] + v.w * sh[4 * q + 3];
        }
        h1s[tid] = fmaxf(acc, 0.f);
    }
    __syncthreads();
    if (tid < 64) {
        const float4* w = (const float4*)(W2 + ((size_t)task * 64 + tid) * 128);
        float acc = b2[task * 64 + tid];
#pragma unroll
        for (int q = 0; q < 32; q++) {
            float4 v = w[q];
            acc += v.x * h1s[4 * q] + v.y * h1s[4 * q + 1] + v.z * h1s[4 * q + 2] + v.w * h1s[4 * q + 3];
        }
        h2s[tid] = fmaxf(acc, 0.f);
    }
    __syncthreads();
    if (tid < 32) {
        float p = Wo[task * 64 + tid] * h2s[tid] + Wo[task * 64 + tid + 32] * h2s[tid + 32];
#pragma unroll
        for (int o = 16; o > 0; o >>= 1) p += __shfl_xor_sync(0xffffffffu, p, o);
        if (tid == 0) out[b] = p + bo[task];
    }
}

// ---------------- launch ----------------
extern "C" void kernel_launch(void* const* d_in, const int* in_sizes, int n_in,
                              void* d_out, int out_size) {
    const float* x       = (const float*)d_in[0];
    const int*   task_ids= (const int*)d_in[1];
    const float* conv1_w = (const float*)d_in[2];
    const float* conv1_b = (const float*)d_in[3];
    const float* bn1_g   = (const float*)d_in[4];
    const float* bn1_b   = (const float*)d_in[5];
    const float* conv2_w = (const float*)d_in[6];
    const float* conv2_b = (const float*)d_in[7];
    const float* bn2_g   = (const float*)d_in[8];
    const float* bn2_b   = (const float*)d_in[9];
    const float* wih     = (const float*)d_in[10];
    const float* whh     = (const float*)d_in[11];
    const float* bih     = (const float*)d_in[12];
    const float* bhh     = (const float*)d_in[13];
    const float* W1      = (const float*)d_in[14];
    const float* b1      = (const float*)d_in[15];
    const float* W2      = (const float*)d_in[16];
    const float* b2      = (const float*)d_in[17];
    const float* Wo      = (const float*)d_in[18];
    const float* bo      = (const float*)d_in[19];
    float* out = (float*)d_out;

    cudaFuncSetAttribute(k3_fused, cudaFuncAttributeMaxDynamicSharedMemorySize, K3_SMEM);
    cudaFuncSetAttribute(k5_xgates, cudaFuncAttributeMaxDynamicSharedMemorySize, K5_SMEM);

    kprep<<<97, 256>>>(wih, conv2_w);
    k1_pstats<<<1024, 256>>>(x);
    k3_fused<<<dim3(2, BB), 256, K3_SMEM>>>(x, conv1_w, conv1_b, bn1_g, bn1_b, conv2_b);
    k5_xgates<<<2048, 256, K5_SMEM>>>(bn2_g, bn2_b, bih, bhh);
    k6_lstm<<<128, 256>>>(whh);
    k8_heads<<<BB, 128>>>(task_ids, W1, b1, W2, b2, Wo, bo, out);
}

// round 16
// speedup vs baseline: 1.5147x; 1.0254x over previous
#include <cuda_runtime.h>
#include <cuda_bf16.h>
#include <cstdint>

#define BB 1024
#define TT 512
#define L1P 511
#define P1 256
#define C1N 128
#define C2N 64
#define L2 128
#define HID 64
#define NG 256
#define EPSV 1e-5f

typedef unsigned long long ull;

// ---------------- device scratch ----------------
__device__ float g_y2[BB * P1 * C2N];        // conv2 output [b][p][c]
__device__ float g_xg[(size_t)L2 * BB * NG]; // xgates [t][b][g]
__device__ float g_shared[BB * HID];
__device__ float g_wihT[HID * NG];           // wih transposed [k][g]
__device__ float g_w2T[C1N * C2N];           // conv2 weights transposed [k][c]
__device__ float g_pstats[16];
__device__ float g_c2sum[C2N], g_c2sq[C2N];

__device__ __forceinline__ float sigm(float v) { return __fdividef(1.f, 1.f + __expf(-v)); }
__device__ __forceinline__ float tanhx(float v) { return 1.f - __fdividef(2.f, __expf(2.f * v) + 1.f); }

// ---- f32x2 packed math helpers ----
__device__ __forceinline__ ull pk2(float a, float b) {
    ull r; asm("mov.b64 %0,{%1,%2};" : "=l"(r) : "f"(a), "f"(b)); return r;
}
__device__ __forceinline__ ull dup2(float a) {
    ull r; asm("mov.b64 %0,{%1,%1};" : "=l"(r) : "f"(a)); return r;
}
__device__ __forceinline__ void upk2(ull v, float& a, float& b) {
    asm("mov.b64 {%0,%1},%2;" : "=f"(a), "=f"(b) : "l"(v));
}
__device__ __forceinline__ ull ffma2(ull a, ull b, ull c) {
    ull d; asm("fma.rn.f32x2 %0,%1,%2,%3;" : "=l"(d) : "l"(a), "l"(b), "l"(c)); return d;
}

// ---------------- KPrep: transposes + zeroing ----------------
__global__ void kprep(const float* __restrict__ wih, const float* __restrict__ w2) {
    int bid = blockIdx.x;
    int tid = threadIdx.x;
    if (bid < 64) {
        int idx = bid * 256 + tid;
        int g = idx >> 6, k = idx & 63;
        g_wihT[k * NG + g] = wih[idx];
    } else if (bid < 96) {
        int idx = (bid - 64) * 256 + tid;
        int k = idx >> 6, c = idx & 63;
        g_w2T[idx] = w2[c * C1N + k];
    } else {
        if (tid < 16) g_pstats[tid] = 0.f;
        if (tid >= 32 && tid < 96) { g_c2sum[tid - 32] = 0.f; g_c2sq[tid - 32] = 0.f; }
    }
}

// ---------------- K1: patch statistics (block-reduced atomics) ----------------
__global__ void __launch_bounds__(256) k1_pstats(const float* __restrict__ x) {
    __shared__ float red[8][14];
    const float2* x2 = (const float2*)x;
    float v[14];
#pragma unroll
    for (int i = 0; i < 14; i++) v[i] = 0.f;
    int total = BB * L1P;
    int stride = gridDim.x * blockDim.x;
#pragma unroll 4
    for (int idx = blockIdx.x * blockDim.x + threadIdx.x; idx < total; idx += stride) {
        int b = idx / L1P;
        int t = idx - b * L1P;
        float2 a = x2[b * TT + t];
        float2 c = x2[b * TT + t + 1];
        float p0 = a.x, p1 = a.y, p2 = c.x, p3 = c.y;
        v[0] += p0; v[1] += p1; v[2] += p2; v[3] += p3;
        v[4] += p0 * p0; v[5] += p0 * p1; v[6] += p0 * p2; v[7] += p0 * p3;
        v[8] += p1 * p1; v[9] += p1 * p2; v[10] += p1 * p3;
        v[11] += p2 * p2; v[12] += p2 * p3; v[13] += p3 * p3;
    }
    int wid = threadIdx.x >> 5, lane = threadIdx.x & 31;
#pragma unroll
    for (int i = 0; i < 14; i++) {
        float s = v[i];
#pragma unroll
        for (int o = 16; o > 0; o >>= 1) s += __shfl_xor_sync(0xffffffffu, s, o);
        if (lane == 0) red[wid][i] = s;
    }
    __syncthreads();
    if (threadIdx.x < 14) {
        int i = threadIdx.x;
        float s = red[0][i] + red[1][i] + red[2][i] + red[3][i]
                + red[4][i] + red[5][i] + red[6][i] + red[7][i];
        atomicAdd(&g_pstats[i], s);
    }
}

// ---------------- K3: conv1+BN1+ReLU+pool1+conv2 fused (+BN2 stat accum) ----------------
#define K3_HS   0
#define K3_WT   16896
#define K3_XS   25088
#define K3_SW   25608
#define K3_D1   26120
#define K3_B2   26248
#define K3_SUM  26312
#define K3_SQ   26376
#define K3_FLTS 26440
#define K3_SMEM (K3_FLTS * 4)

__global__ void __launch_bounds__(256, 1) k3_fused(const float* __restrict__ x,
                                                   const float* __restrict__ w1,
                                                   const float* __restrict__ b1,
                                                   const float* __restrict__ g1,
                                                   const float* __restrict__ be1,
                                                   const float* __restrict__ b2) {
    extern __shared__ float sm3[];
    float* hs = sm3 + K3_HS;
    float* wt2T = sm3 + K3_WT;
    float* xs = sm3 + K3_XS;
    float* sw = sm3 + K3_SW;
    float* D1s = sm3 + K3_D1;
    float* b2s = sm3 + K3_B2;
    float* ssum = sm3 + K3_SUM;
    float* ssq = sm3 + K3_SQ;
    int tid = threadIdx.x;
    int b = blockIdx.y;
    int p0 = blockIdx.x * 128;

    if (tid < 128) {
        int c = tid;
        float N = (float)(BB * L1P);
        float m0 = g_pstats[0] / N, m1 = g_pstats[1] / N, m2 = g_pstats[2] / N, m3 = g_pstats[3] / N;
        float M00 = g_pstats[4] / N, M01 = g_pstats[5] / N, M02 = g_pstats[6] / N, M03 = g_pstats[7] / N;
        float M11 = g_pstats[8] / N, M12 = g_pstats[9] / N, M13 = g_pstats[10] / N;
        float M22 = g_pstats[11] / N, M23 = g_pstats[12] / N, M33 = g_pstats[13] / N;
        float v0 = w1[c * 4 + 0], v1 = w1[c * 4 + 2], v2 = w1[c * 4 + 1], v3 = w1[c * 4 + 3];
        float bc = b1[c];
        float vm = v0 * m0 + v1 * m1 + v2 * m2 + v3 * m3;
        float mean = vm + bc;
        float q = v0 * v0 * M00 + v1 * v1 * M11 + v2 * v2 * M22 + v3 * v3 * M33
                + 2.f * (v0 * v1 * M01 + v0 * v2 * M02 + v0 * v3 * M03
                       + v1 * v2 * M12 + v1 * v3 * M13 + v2 * v3 * M23);
        float ey2 = q + 2.f * bc * vm + bc * bc;
        float var = ey2 - mean * mean;
        float A = g1[c] * rsqrtf(var + EPSV);
        float D = be1[c] + A * (bc - mean);
        sw[c * 4 + 0] = A * v0;
        sw[c * 4 + 1] = A * v1;
        sw[c * 4 + 2] = A * v2;
        sw[c * 4 + 3] = A * v3;
        D1s[c] = D;
    }
    if (tid < 64) { b2s[tid] = b2[tid]; ssum[tid] = 0.f; ssq[tid] = 0.f; }
    {
        int tlo = 2 * p0 - 1;
        const float2* x2 = (const float2*)x;
        for (int j = tid; j < 258; j += 256) {
            int t = tlo + j;
            float2 vv = (t >= 0 && t < TT) ? x2[b * TT + t] : make_float2(0.f, 0.f);
            xs[2 * j] = vv.x;
            xs[2 * j + 1] = vv.y;
        }
    }
    {
        const float4* s4 = (const float4*)g_w2T;
        float4* d4 = (float4*)wt2T;
        for (int idx = tid; idx < C1N * C2N / 4; idx += 256) d4[idx] = s4[idx];
    }
    __syncthreads();

    const float4* xs4 = (const float4*)xs;
    for (int idx = tid; idx < C1N * 128; idx += 256) {
        int p = idx & 127, c = idx >> 7;
        float4 q1 = xs4[p];
        float4 q2 = xs4[p + 1];
        float s0 = sw[c * 4], s1 = sw[c * 4 + 1], s2 = sw[c * 4 + 2], s3 = sw[c * 4 + 3];
        float D = D1s[c];
        float z2 = fmaf(s0, q1.z, fmaf(s1, q1.w, fmaf(s2, q2.x, fmaf(s3, q2.y, D))));
        float z;
        if (p0 + p == 0) {
            z = z2;
        } else {
            float z1 = fmaf(s0, q1.x, fmaf(s1, q1.y, fmaf(s2, q1.z, fmaf(s3, q1.w, D))));
            z = fmaxf(z1, z2);
        }
        hs[c * 132 + p] = fmaxf(z, 0.f);
    }
    __syncthreads();

    int lane = tid & 31, w = tid >> 5;
    int pq2 = lane & 3, cq2 = lane >> 2;
    int pbase = w * 16 + pq2 * 4;
    int cbase = cq2 * 8;
    ull acc2[2][8];
#pragma unroll
    for (int i = 0; i < 2; i++)
#pragma unroll
        for (int j = 0; j < 8; j++) acc2[i][j] = 0ull;
#pragma unroll 4
    for (int k = 0; k < C1N; k++) {
        ulonglong2 hv = *(const ulonglong2*)&hs[k * 132 + pbase];
        float4 w0 = *(const float4*)&wt2T[k * C2N + cbase];
        float4 w1q = *(const float4*)&wt2T[k * C2N + cbase + 4];
        const float* w0f = (const float*)&w0;
        const float* w1f = (const float*)&w1q;
#pragma unroll
        for (int j = 0; j < 4; j++) {
            ull wd = dup2(w0f[j]);
            acc2[0][j] = ffma2(wd, hv.x, acc2[0][j]);
            acc2[1][j] = ffma2(wd, hv.y, acc2[1][j]);
        }
#pragma unroll
        for (int j = 0; j < 4; j++) {
            ull wd = dup2(w1f[j]);
            acc2[0][j + 4] = ffma2(wd, hv.x, acc2[0][j + 4]);
            acc2[1][j + 4] = ffma2(wd, hv.y, acc2[1][j + 4]);
        }
    }
    float csum[8], csq[8];
#pragma unroll
    for (int j = 0; j < 8; j++) { csum[j] = 0.f; csq[j] = 0.f; }
#pragma unroll
    for (int pr = 0; pr < 2; pr++) {
        float lo[8], hi[8];
#pragma unroll
        for (int j = 0; j < 8; j++) upk2(acc2[pr][j], lo[j], hi[j]);
#pragma unroll
        for (int half = 0; half < 2; half++) {
            int P = p0 + pbase + pr * 2 + half;
            float* src = half ? hi : lo;
            float4 o0, o1;
            float* q0 = (float*)&o0;
            float* q1 = (float*)&o1;
#pragma unroll
            for (int j = 0; j < 4; j++) {
                float v0 = src[j] + b2s[cbase + j];
                float v1 = src[j + 4] + b2s[cbase + 4 + j];
                q0[j] = v0; q1[j] = v1;
                csum[j] += v0; csq[j] += v0 * v0;
                csum[j + 4] += v1; csq[j + 4] += v1 * v1;
            }
            float* dst = &g_y2[((size_t)b * P1 + P) * C2N + cbase];
            *(float4*)dst = o0;
            *(float4*)(dst + 4) = o1;
        }
    }
#pragma unroll
    for (int o = 1; o <= 2; o <<= 1) {
#pragma unroll
        for (int j = 0; j < 8; j++) {
            csum[j] += __shfl_xor_sync(0xffffffffu, csum[j], o);
            csq[j] += __shfl_xor_sync(0xffffffffu, csq[j], o);
        }
    }
    if (pq2 == 0) {
#pragma unroll
        for (int j = 0; j < 8; j++) {
            atomicAdd(&ssum[cbase + j], csum[j]);
            atomicAdd(&ssq[cbase + j], csq[j]);
        }
    }
    __syncthreads();
    if (tid < 64) {
        atomicAdd(&g_c2sum[tid], ssum[tid]);
        atomicAdd(&g_c2sq[tid], ssq[tid]);
    }
}

// ---------------- K5 v3: xgates GEMM, gate-halved tiles for occupancy ----------------
// grid 4096: bid = (row-tile rblk, gate-half gh). Block: 64 rows x 128 gates.
// smem floats: WSM[64][128]=8192 | SS[64][68]=4352 | C2[64] | D2[64] | BS[128]
#define K5_W    0
#define K5_SS   8192
#define K5_C2   12544
#define K5_D2   12608
#define K5_BS   12672
#define K5_FLTS 12800
#define K5_SMEM (K5_FLTS * 4)

__global__ void __launch_bounds__(256) k5_xgates(const float* __restrict__ g2,
                                                 const float* __restrict__ be2,
                                                 const float* __restrict__ bih,
                                                 const float* __restrict__ bhh) {
    extern __shared__ float sm5[];
    float* wsm = sm5 + K5_W;   // [k=64][g=128] (this half)
    float* ss = sm5 + K5_SS;   // [k=64][r stride 68]
    float* C2s = sm5 + K5_C2;
    float* D2s = sm5 + K5_D2;
    float* bs = sm5 + K5_BS;
    int tid = threadIdx.x;
    int bid = blockIdx.x;
    int rblk = bid >> 1;
    int G0 = (bid & 1) << 7;   // 0 or 128
    int r0 = rblk * 64;
    int b = r0 >> 7;
    int l0 = r0 & 127;

    if (tid < 64) {
        float N = (float)(BB * P1);
        float mean = g_c2sum[tid] / N;
        float var = g_c2sq[tid] / N - mean * mean;
        float A = g2[tid] * rsqrtf(var + EPSV);
        C2s[tid] = A;
        D2s[tid] = be2[tid] - A * mean;
    }
    if (tid < 128) bs[tid] = bih[G0 + tid] + bhh[G0 + tid];
    // weight half tile: wsm[k][0..128) = g_wihT[k][G0..G0+128)
    {
        for (int idx = tid; idx < HID * 32; idx += 256) {
            int k = idx >> 5, c4 = idx & 31;
            *(float4*)&wsm[k * 128 + c4 * 4] =
                *(const float4*)&g_wihT[k * NG + G0 + c4 * 4];
        }
    }
    __syncthreads();
    for (int idx = tid; idx < 64 * 16; idx += 256) {
        int rl = idx >> 4, cq = idx & 15;
        int l = l0 + rl;
        const float4* ya4 = (const float4*)&g_y2[((size_t)b * P1 + 2 * l) * C2N];
        float4 ya = ya4[cq];
        float4 yb = ya4[16 + cq];
        float av[4] = {ya.x, ya.y, ya.z, ya.w};
        float bv[4] = {yb.x, yb.y, yb.z, yb.w};
#pragma unroll
        for (int j = 0; j < 4; j++) {
            int c = cq * 4 + j;
            float za = fmaf(C2s[c], av[j], D2s[c]);
            float zb = fmaf(C2s[c], bv[j], D2s[c]);
            ss[c * 68 + rl] = fmaxf(fmaxf(za, zb), 0.f);
        }
    }
    __syncthreads();
    // GEMM: warp = 8 rows (ro), lane = 4 gates (go*4 within half)
    int ro = tid >> 5, go = tid & 31;
    ull acc2[4][4];
#pragma unroll
    for (int i = 0; i < 4; i++)
#pragma unroll
        for (int j = 0; j < 4; j++) acc2[i][j] = 0ull;
#pragma unroll 4
    for (int k = 0; k < HID; k++) {
        ulonglong2 hA = *(const ulonglong2*)&ss[k * 68 + ro * 8];
        ulonglong2 hB = *(const ulonglong2*)&ss[k * 68 + ro * 8 + 4];
        float4 w0 = *(const float4*)&wsm[k * 128 + go * 4];
        const float* w0f = (const float*)&w0;
#pragma unroll
        for (int j = 0; j < 4; j++) {
            ull wd = dup2(w0f[j]);
            acc2[0][j] = ffma2(wd, hA.x, acc2[0][j]);
            acc2[1][j] = ffma2(wd, hA.y, acc2[1][j]);
            acc2[2][j] = ffma2(wd, hB.x, acc2[2][j]);
            acc2[3][j] = ffma2(wd, hB.y, acc2[3][j]);
        }
    }
#pragma unroll
    for (int pr = 0; pr < 4; pr++) {
        float lo[4], hi[4];
#pragma unroll
        for (int j = 0; j < 4; j++) upk2(acc2[pr][j], lo[j], hi[j]);
        int l = l0 + ro * 8 + pr * 2;
        int gofs = G0 + go * 4;
        float4 a0, b0q;
        float* pa0 = (float*)&a0;
        float* pb0 = (float*)&b0q;
#pragma unroll
        for (int j = 0; j < 4; j++) {
            pa0[j] = lo[j] + bs[go * 4 + j];
            pb0[j] = hi[j] + bs[go * 4 + j];
        }
        *(float4*)&g_xg[((size_t)l * BB + b) * NG + gofs] = a0;
        *(float4*)&g_xg[((size_t)(l + 1) * BB + b) * NG + gofs] = b0q;
    }
}

// ---------------- K6: LSTM recurrence (f32x2, 8 rows/block) ----------------
__global__ void __launch_bounds__(256, 1) k6_lstm(const float* __restrict__ whh) {
    __shared__ float G[8 * 256];
    __shared__ __align__(16) float hsm[HID * 8];  // [k][r]
    int tid = threadIdx.x;
    int b0 = blockIdx.x * 8;
    int g = tid;
    ull wpack[64];
    {
        const float4* w4 = (const float4*)(whh + (size_t)g * 64);
#pragma unroll
        for (int q = 0; q < 16; q++) {
            float4 v = w4[q];
            wpack[4 * q] = dup2(v.x);
            wpack[4 * q + 1] = dup2(v.y);
            wpack[4 * q + 2] = dup2(v.z);
            wpack[4 * q + 3] = dup2(v.w);
        }
    }
    for (int idx = tid; idx < HID * 8; idx += 256) hsm[idx] = 0.f;
    int r_u = tid >> 5, lane = tid & 31;
    float c0 = 0.f, c1 = 0.f, hsum0 = 0.f, hsum1 = 0.f;
    float xv[8];
#pragma unroll
    for (int r = 0; r < 8; r++) xv[r] = g_xg[(size_t)(b0 + r) * NG + g];
    __syncthreads();
    for (int t = 0; t < L2; t++) {
        ull acc2[4];
#pragma unroll
        for (int p = 0; p < 4; p++) acc2[p] = pk2(xv[2 * p], xv[2 * p + 1]);
#pragma unroll
        for (int k = 0; k < HID; k++) {
            ulonglong2 hA = *(const ulonglong2*)&hsm[k * 8];
            ulonglong2 hB = *(const ulonglong2*)&hsm[k * 8 + 4];
            acc2[0] = ffma2(wpack[k], hA.x, acc2[0]);
            acc2[1] = ffma2(wpack[k], hA.y, acc2[1]);
            acc2[2] = ffma2(wpack[k], hB.x, acc2[2]);
            acc2[3] = ffma2(wpack[k], hB.y, acc2[3]);
        }
        if (t + 1 < L2) {
#pragma unroll
            for (int r = 0; r < 8; r++)
                xv[r] = g_xg[((size_t)(t + 1) * BB + b0 + r) * NG + g];
        }
#pragma unroll
        for (int p = 0; p < 4; p++) {
            float a, bq;
            upk2(acc2[p], a, bq);
            G[(2 * p) * 256 + g] = a;
            G[(2 * p + 1) * 256 + g] = bq;
        }
        __syncthreads();
        {
            int r = r_u;
            float gi0 = G[r * 256 + lane],       gi1 = G[r * 256 + lane + 32];
            float gf0 = G[r * 256 + 64 + lane],  gf1 = G[r * 256 + 96 + lane];
            float gg0 = G[r * 256 + 128 + lane], gg1 = G[r * 256 + 160 + lane];
            float go0 = G[r * 256 + 192 + lane], go1 = G[r * 256 + 224 + lane];
            c0 = sigm(gf0) * c0 + sigm(gi0) * tanhx(gg0);
            c1 = sigm(gf1) * c1 + sigm(gi1) * tanhx(gg1);
            float h0 = sigm(go0) * tanhx(c0);
            float h1 = sigm(go1) * tanhx(c1);
            hsum0 += h0; hsum1 += h1;
            hsm[lane * 8 + r] = h0;
            hsm[(lane + 32) * 8 + r] = h1;
        }
        __syncthreads();
    }
    g_shared[(b0 + r_u) * 64 + lane] = hsum0 * (1.f / 128.f);
    g_shared[(b0 + r_u) * 64 + lane + 32] = hsum1 * (1.f / 128.f);
}

// ---------------- K8: task-routed heads ----------------
__global__ void __launch_bounds__(128) k8_heads(const int* __restrict__ task_ids,
                                                const float* __restrict__ W1, const float* __restrict__ b1,
                                                const float* __restrict__ W2, const float* __restrict__ b2,
                                                const float* __restrict__ Wo, const float* __restrict__ bo,
                                                float* __restrict__ out) {
    __shared__ float sh[64], h1s[128], h2s[64];
    int b = blockIdx.x, tid = threadIdx.x;
    if (tid < 64) sh[tid] = g_shared[b * 64 + tid];
    __syncthreads();
    int task = task_ids[b];
    {
        const float4* w = (const float4*)(W1 + ((size_t)task * 128 + tid) * 64);
        float acc = b1[task * 128 + tid];
#pragma unroll
        for (int q = 0; q < 16; q++) {
            float4 v = w[q];
            acc += v.x * sh[4 * q] + v.y * sh[4 * q + 1] + v.z * sh[4 * q + 2] + v.w * sh[4 * q + 3];
        }
        h1s[tid] = fmaxf(acc, 0.f);
    }
    __syncthreads();
    if (tid < 64) {
        const float4* w = (const float4*)(W2 + ((size_t)task * 64 + tid) * 128);
        float acc = b2[task * 64 + tid];
#pragma unroll
        for (int q = 0; q < 32; q++) {
            float4 v = w[q];
            acc += v.x * h1s[4 * q] + v.y * h1s[4 * q + 1] + v.z * h1s[4 * q + 2] + v.w * h1s[4 * q + 3];
        }
        h2s[tid] = fmaxf(acc, 0.f);
    }
    __syncthreads();
    if (tid < 32) {
        float p = Wo[task * 64 + tid] * h2s[tid] + Wo[task * 64 + tid + 32] * h2s[tid + 32];
#pragma unroll
        for (int o = 16; o > 0; o >>= 1) p += __shfl_xor_sync(0xffffffffu, p, o);
        if (tid == 0) out[b] = p + bo[task];
    }
}

// ---------------- launch ----------------
extern "C" void kernel_launch(void* const* d_in, const int* in_sizes, int n_in,
                              void* d_out, int out_size) {
    const float* x       = (const float*)d_in[0];
    const int*   task_ids= (const int*)d_in[1];
    const float* conv1_w = (const float*)d_in[2];
    const float* conv1_b = (const float*)d_in[3];
    const float* bn1_g   = (const float*)d_in[4];
    const float* bn1_b   = (const float*)d_in[5];
    const float* conv2_w = (const float*)d_in[6];
    const float* conv2_b = (const float*)d_in[7];
    const float* bn2_g   = (const float*)d_in[8];
    const float* bn2_b   = (const float*)d_in[9];
    const float* wih     = (const float*)d_in[10];
    const float* whh     = (const float*)d_in[11];
    const float* bih     = (const float*)d_in[12];
    const float* bhh     = (const float*)d_in[13];
    const float* W1      = (const float*)d_in[14];
    const float* b1      = (const float*)d_in[15];
    const float* W2      = (const float*)d_in[16];
    const float* b2      = (const float*)d_in[17];
    const float* Wo      = (const float*)d_in[18];
    const float* bo      = (const float*)d_in[19];
    float* out = (float*)d_out;

    cudaFuncSetAttribute(k3_fused, cudaFuncAttributeMaxDynamicSharedMemorySize, K3_SMEM);
    cudaFuncSetAttribute(k5_xgates, cudaFuncAttributeMaxDynamicSharedMemorySize, K5_SMEM);

    kprep<<<97, 256>>>(wih, conv2_w);
    k1_pstats<<<1024, 256>>>(x);
    k3_fused<<<dim3(2, BB), 256, K3_SMEM>>>(x, conv1_w, conv1_b, bn1_g, bn1_b, conv2_b);
    k5_xgates<<<4096, 256, K5_SMEM>>>(bn2_g, bn2_b, bih, bhh);
    k6_lstm<<<128, 256>>>(whh);
    k8_heads<<<BB, 128>>>(task_ids, W1, b1, W2, b2, Wo, bo, out);
}